// round 12
// baseline (speedup 1.0000x reference)
#include <cuda_runtime.h>
#include <cuda_fp16.h>
#include <math.h>
#include <stdint.h>

#define NTOK 8192
#define DDIM 1024
#define NSEM 8192
#define NLRN 128
#define NCB  8320           // NSEM + NLRN = 65 * 128 exactly
#define NXT  65             // column tiles (exact, no padding)
#define NCAND (NXT * 2)     // 130 top-2-per-tile candidates per row

#define TILE_M 128
#define TILE_N 128
#define BK     64           // fp16 elems per K-chunk (128B row)
#define NKCH   (DDIM / BK)  // 16
#define STAGES 3
#define A_BYTES (TILE_M * 128)            // 16KB
#define B_BYTES (TILE_N * 128)            // 16KB
#define STAGE_BYTES (A_BYTES + B_BYTES)   // 32KB
#define RED_BYTES 4096
#define SMEM_TOTAL (STAGES * STAGE_BYTES + RED_BYTES)  // 100KB -> 2 CTAs/SM

// ---------------- scratch (__device__ globals; no allocs) -------------------
__device__ __align__(128) float  g_xn[(size_t)NTOK * DDIM];
__device__ __align__(128) float  g_cb[(size_t)NCB * DDIM];
__device__ __align__(128) __half g_Ah[(size_t)NTOK * DDIM];
__device__ __align__(128) __half g_Bh[(size_t)NCB * DDIM];
__device__ float g_p2val[(size_t)NTOK * NCAND];
__device__ int   g_p2col[(size_t)NTOK * NCAND];
__device__ float g_rowloss[NTOK];
__device__ int   g_idx[NTOK];

// ---------------- PTX helpers ----------------------------------------------
__device__ __forceinline__ uint32_t smem_u32(const void* p) {
    uint32_t a;
    asm("{ .reg .u64 t; cvta.to.shared.u64 t, %1; cvt.u32.u64 %0, t; }" : "=r"(a) : "l"(p));
    return a;
}
__device__ __forceinline__ uint32_t sw128(uint32_t x) { return x ^ ((x >> 3) & 0x70); }

__device__ __forceinline__ void cp_async16(uint32_t dst, const void* src) {
    asm volatile("cp.async.cg.shared.global [%0], [%1], 16;" :: "r"(dst), "l"(src) : "memory");
}
#define CP_COMMIT() asm volatile("cp.async.commit_group;" ::: "memory")
#define CP_WAIT(n)  asm volatile("cp.async.wait_group %0;" :: "n"(n) : "memory")

#define LDSM_X4(r0, r1, r2, r3, a) \
    asm volatile("ldmatrix.sync.aligned.m8n8.x4.shared.b16 {%0,%1,%2,%3}, [%4];" \
                 : "=r"(r0), "=r"(r1), "=r"(r2), "=r"(r3) : "r"(a))

#define MMA16816(c, a, b0, b1) \
    asm volatile("mma.sync.aligned.m16n8k16.row.col.f32.f16.f16.f32 " \
                 "{%0,%1,%2,%3},{%4,%5,%6,%7},{%8,%9},{%0,%1,%2,%3};" \
                 : "+f"((c)[0]), "+f"((c)[1]), "+f"((c)[2]), "+f"((c)[3]) \
                 : "r"((a)[0]), "r"((a)[1]), "r"((a)[2]), "r"((a)[3]), "r"(b0), "r"(b1))

// top-2 insert keeping (value desc, col asc) order
#define TOP2_INS(v, c, v1, c1, v2, c2) do {                                  \
    float _v = (v); int _c = (c);                                            \
    if (_v > (v1) || (_v == (v1) && _c < (c1))) {                            \
        (v2) = (v1); (c2) = (c1); (v1) = _v; (c1) = _c;                      \
    } else if (_v > (v2) || (_v == (v2) && _c < (c2))) {                     \
        (v2) = _v; (c2) = _c;                                                \
    }                                                                        \
} while (0)

// ---------------------------------------------------------------------------
// row L2-normalize -> f32 copy + fp16 copy
// ---------------------------------------------------------------------------
__global__ void norm_cast(const float* __restrict__ src, float* __restrict__ f32dst,
                          __half* __restrict__ hdst) {
    int r = blockIdx.x;
    int t = threadIdx.x;
    float4 v = ((const float4*)(src + (size_t)r * DDIM))[t];
    float ss = v.x * v.x + v.y * v.y + v.z * v.z + v.w * v.w;
    #pragma unroll
    for (int o = 16; o; o >>= 1) ss += __shfl_xor_sync(0xffffffffu, ss, o);
    __shared__ float red[8];
    __shared__ float inv_s;
    if ((t & 31) == 0) red[t >> 5] = ss;
    __syncthreads();
    if (t == 0) {
        float s = 0.f;
        #pragma unroll
        for (int i = 0; i < 8; i++) s += red[i];
        inv_s = 1.0f / fmaxf(sqrtf(s), 1e-8f);
    }
    __syncthreads();
    float inv = inv_s;
    float f[4] = { v.x * inv, v.y * inv, v.z * inv, v.w * inv };
    ((float4*)(f32dst + (size_t)r * DDIM))[t] = *(float4*)f;
    union { __half h[4]; uint2 u; } p;
    #pragma unroll
    for (int j = 0; j < 4; j++) p.h[j] = __float2half_rn(f[j]);
    *(uint2*)(hdst + (size_t)r * DDIM + 4 * t) = p.u;
}

// ---------------------------------------------------------------------------
// fp16 mma.sync GEMM (K=1024) + fused per-tile top-2 row argmax.
// CTA 128x128, 4 warps (2x2), warp tile 64x64, BK=64, 3-stage cp.async,
// 2 CTAs/SM, two column tiles per CTA in one continuous pipeline.
// NEW: register double-buffered fragments — LDSM for ks+1 overlaps MMAs of ks.
// ---------------------------------------------------------------------------
__device__ __forceinline__ void load_chunk(const __half* __restrict__ Ah,
                                           const __half* __restrict__ Bh,
                                           uint32_t data_base, int stage,
                                           int by, int bxe, int kc, int tid) {
    uint32_t sb = data_base + stage * STAGE_BYTES;
    const char* Ab = (const char*)Ah + (size_t)by * TILE_M * (DDIM * 2) + (size_t)kc * 128;
    const char* Bb = (const char*)Bh + (size_t)bxe * TILE_N * (DDIM * 2) + (size_t)kc * 128;
    #pragma unroll
    for (int i = 0; i < 8; i++) {
        int c = tid + i * 128;          // 0..1023
        int row = c >> 3, cg = c & 7;
        cp_async16(sb + sw128(row * 128 + cg * 16),
                   Ab + (size_t)row * (DDIM * 2) + cg * 16);
    }
    #pragma unroll
    for (int i = 0; i < 8; i++) {
        int c = tid + i * 128;
        int row = c >> 3, cg = c & 7;
        cp_async16(sb + A_BYTES + sw128(row * 128 + cg * 16),
                   Bb + (size_t)row * (DDIM * 2) + cg * 16);
    }
    CP_COMMIT();
}

__global__ void __launch_bounds__(128, 2)
gemm_mma(const __half* __restrict__ Ah, const __half* __restrict__ Bh,
         float* __restrict__ Cout) {
    extern __shared__ char smem[];
    uint32_t data_base = smem_u32(smem);
    float* bufv = (float*)(smem + STAGES * STAGE_BYTES);          // [128][2][2]
    int*   bufi = (int*)(smem + STAGES * STAGE_BYTES + 2048);     // [128][2][2]

    int tid = threadIdx.x, wid = tid >> 5, lane = tid & 31;
    int bx = blockIdx.x, by = blockIdx.y;
    int warp_m = wid & 1;       // 2 warps over M (64 rows each)
    int warp_n = wid >> 1;      // 2 warps over N (64 cols each)

    int rowA = lane & 15;
    int kselA = (lane >> 4) * 16;
    int rowB = (lane & 7) + ((lane >> 4) & 1) * 8;
    int kselB = ((lane >> 3) & 1) * 16;

    // per-lane swizzled byte offsets, relative to stage base
    uint32_t aoff[4], boff[4];
    #pragma unroll
    for (int mt = 0; mt < 4; mt++)
        aoff[mt] = sw128((uint32_t)(warp_m * 64 + mt * 16 + rowA) * 128 + kselA);
    #pragma unroll
    for (int np = 0; np < 4; np++)
        boff[np] = sw128((uint32_t)(warp_n * 64 + np * 16 + rowB) * 128 + kselB);
    // note: ks advances by 32 bytes; sw128 only permutes bits[6:4] via bits[9:7],
    // and +ks*32 changes bit5 -> must apply sw128 to full offset. Recompute per ks
    // by XOR trick: sw128(base + ks*32) != sw128(base)+ks*32 in general, so
    // keep full recompute (cheap ALU, hidden under MMAs).

    int ntiles = (bx <= 31) ? 2 : 1;       // bx in 0..32; pair (bx, bx+33)
    int NKT = ntiles * NKCH;

    float acc[4][8][4];
    #pragma unroll
    for (int i = 0; i < 4; i++)
        #pragma unroll
        for (int j = 0; j < 8; j++)
            #pragma unroll
            for (int q = 0; q < 4; q++) acc[i][j][q] = 0.f;

    load_chunk(Ah, Bh, data_base, 0, by, bx, 0, tid);
    load_chunk(Ah, Bh, data_base, 1, by, bx, 1, tid);

    uint32_t afr[2][4][4], bfr[2][4][4];

    for (int g = 0; g < NKT; g++) {
        if (g + 1 < NKT) CP_WAIT(1); else CP_WAIT(0);
        __syncthreads();
        if (g + 2 < NKT) {
            int gi = g + 2;
            load_chunk(Ah, Bh, data_base, gi % STAGES, by, bx + (gi >> 4) * 33,
                       gi & (NKCH - 1), tid);
        }
        uint32_t Ab = data_base + (g % STAGES) * STAGE_BYTES;
        uint32_t Bb = Ab + A_BYTES;

        // preload fragments for ks=0
        #pragma unroll
        for (int mt = 0; mt < 4; mt++) {
            uint32_t off = sw128((uint32_t)(warp_m * 64 + mt * 16 + rowA) * 128 + kselA);
            LDSM_X4(afr[0][mt][0], afr[0][mt][1], afr[0][mt][2], afr[0][mt][3], Ab + off);
        }
        #pragma unroll
        for (int np = 0; np < 4; np++) {
            uint32_t off = sw128((uint32_t)(warp_n * 64 + np * 16 + rowB) * 128 + kselB);
            LDSM_X4(bfr[0][np][0], bfr[0][np][1], bfr[0][np][2], bfr[0][np][3], Bb + off);
        }

        #pragma unroll
        for (int ks = 0; ks < 4; ks++) {
            const int cb = ks & 1, nb = cb ^ 1;
            if (ks < 3) {   // prefetch fragments for ks+1 (overlaps MMAs below)
                #pragma unroll
                for (int mt = 0; mt < 4; mt++) {
                    uint32_t off = sw128((uint32_t)(warp_m * 64 + mt * 16 + rowA) * 128
                                         + (ks + 1) * 32 + kselA);
                    LDSM_X4(afr[nb][mt][0], afr[nb][mt][1], afr[nb][mt][2], afr[nb][mt][3],
                            Ab + off);
                }
                #pragma unroll
                for (int np = 0; np < 4; np++) {
                    uint32_t off = sw128((uint32_t)(warp_n * 64 + np * 16 + rowB) * 128
                                         + (ks + 1) * 32 + kselB);
                    LDSM_X4(bfr[nb][np][0], bfr[nb][np][1], bfr[nb][np][2], bfr[nb][np][3],
                            Bb + off);
                }
            }
            #pragma unroll
            for (int mt = 0; mt < 4; mt++)
                #pragma unroll
                for (int nt = 0; nt < 8; nt++)
                    MMA16816(acc[mt][nt], afr[cb][mt],
                             bfr[cb][nt >> 1][(nt & 1) * 2], bfr[cb][nt >> 1][(nt & 1) * 2 + 1]);
        }

        if ((g & (NKCH - 1)) == (NKCH - 1)) {
            // ============ epilogue for tile (g>>4); overlaps next tile's loads
            int bxe = bx + (g >> 4) * 33;
            int row_base = by * TILE_M + warp_m * 64;
            int col_base = bxe * TILE_N + warp_n * 64;
            #pragma unroll
            for (int mt = 0; mt < 4; mt++) {
                int r0 = row_base + mt * 16 + (lane >> 2);
                #pragma unroll
                for (int nt = 0; nt < 8; nt++) {
                    int c0 = col_base + nt * 8 + (lane & 3) * 2;
                    float2* p0 = (float2*)(Cout + (size_t)r0 * NCB + c0);
                    float2* p1 = (float2*)(Cout + (size_t)(r0 + 8) * NCB + c0);
                    *p0 = make_float2(acc[mt][nt][0], acc[mt][nt][1]);
                    *p1 = make_float2(acc[mt][nt][2], acc[mt][nt][3]);
                }
            }
            #pragma unroll
            for (int mt = 0; mt < 4; mt++) {
                #pragma unroll
                for (int h = 0; h < 2; h++) {
                    float v1 = -1e30f, v2 = -1e30f;
                    int   c1 = 0x7fffffff, c2 = 0x7fffffff;
                    #pragma unroll
                    for (int nt = 0; nt < 8; nt++) {
                        #pragma unroll
                        for (int qq = 0; qq < 2; qq++) {
                            int colg = col_base + nt * 8 + (lane & 3) * 2 + qq;
                            float v = acc[mt][nt][h * 2 + qq];
                            TOP2_INS(v, colg, v1, c1, v2, c2);
                        }
                    }
                    #pragma unroll
                    for (int off = 1; off <= 2; off <<= 1) {
                        float ov1 = __shfl_xor_sync(0xffffffffu, v1, off);
                        int   oc1 = __shfl_xor_sync(0xffffffffu, c1, off);
                        float ov2 = __shfl_xor_sync(0xffffffffu, v2, off);
                        int   oc2 = __shfl_xor_sync(0xffffffffu, c2, off);
                        TOP2_INS(ov1, oc1, v1, c1, v2, c2);
                        TOP2_INS(ov2, oc2, v1, c1, v2, c2);
                    }
                    if ((lane & 3) == 0) {
                        int rl = warp_m * 64 + mt * 16 + (lane >> 2) + h * 8;
                        bufv[(rl * 2 + warp_n) * 2 + 0] = v1;
                        bufv[(rl * 2 + warp_n) * 2 + 1] = v2;
                        bufi[(rl * 2 + warp_n) * 2 + 0] = c1;
                        bufi[(rl * 2 + warp_n) * 2 + 1] = c2;
                    }
                }
            }
            __syncthreads();
            {
                float v1 = -1e30f, v2 = -1e30f;
                int   c1 = 0x7fffffff, c2 = 0x7fffffff;
                #pragma unroll
                for (int w = 0; w < 2; w++) {
                    TOP2_INS(bufv[(tid * 2 + w) * 2 + 0], bufi[(tid * 2 + w) * 2 + 0], v1, c1, v2, c2);
                    TOP2_INS(bufv[(tid * 2 + w) * 2 + 1], bufi[(tid * 2 + w) * 2 + 1], v1, c1, v2, c2);
                }
                size_t base = ((size_t)(by * TILE_M + tid) * NXT + bxe) * 2;
                g_p2val[base + 0] = v1; g_p2val[base + 1] = v2;
                g_p2col[base + 0] = c1; g_p2col[base + 1] = c2;
            }
            __syncthreads();   // protect bufv/bufi before next tile's epilogue
            #pragma unroll
            for (int i = 0; i < 4; i++)
                #pragma unroll
                for (int j = 0; j < 8; j++)
                    #pragma unroll
                    for (int q = 0; q < 4; q++) acc[i][j][q] = 0.f;
        }
    }
}

// ---------------------------------------------------------------------------
// exact rescoring of near-max candidates (fp64 dot) + gather z_q / z_q_st
// ---------------------------------------------------------------------------
__global__ void rescore_gather(float* __restrict__ idx_out,
                               float* __restrict__ zq,
                               float* __restrict__ zqst) {
    int r = blockIdx.x;
    int t = threadIdx.x;
    __shared__ float  cval[NCAND];
    __shared__ int    ccol[NCAND];
    __shared__ float  smax;
    __shared__ int    ncand;
    __shared__ int    clist[NCAND];
    __shared__ double dred[256];
    __shared__ double sbest;
    __shared__ int    sbestc;

    if (t < NCAND) {
        cval[t] = g_p2val[(size_t)r * NCAND + t];
        ccol[t] = g_p2col[(size_t)r * NCAND + t];
    }
    if (t == 0) ncand = 0;
    __syncthreads();
    if (t == 0) {
        float m = -1e30f;
        #pragma unroll
        for (int i = 0; i < NCAND; i++) m = fmaxf(m, cval[i]);
        smax = m;
    }
    __syncthreads();
    if (t < NCAND && cval[t] >= smax - 1.5e-4f && ccol[t] < NCB) {
        int s = atomicAdd(&ncand, 1);
        clist[s] = ccol[t];
    }
    __syncthreads();

    int n = ncand;
    double bestv = -1e30; int bestc = 0x7fffffff;
    const float4 xv = ((const float4*)(g_xn + (size_t)r * DDIM))[t];
    for (int i = 0; i < n; i++) {
        int c = clist[i];
        const float4 cv = ((const float4*)(g_cb + (size_t)c * DDIM))[t];
        double d = (double)xv.x * cv.x + (double)xv.y * cv.y
                 + (double)xv.z * cv.z + (double)xv.w * cv.w;
        dred[t] = d;
        __syncthreads();
        #pragma unroll
        for (int off = 128; off; off >>= 1) {
            if (t < off) dred[t] += dred[t + off];
            __syncthreads();
        }
        double tot = dred[0];
        __syncthreads();
        if (tot > bestv || (tot == bestv && c < bestc)) { bestv = tot; bestc = c; }
    }
    if (t == 0) { sbest = bestv; sbestc = bestc; }
    __syncthreads();
    bestc = sbestc; bestv = sbest;

    if (t == 0) {
        idx_out[r]   = (float)bestc;
        g_idx[r]     = bestc;
        g_rowloss[r] = 1.0f - (float)bestv;
    }
    const float4 cv = ((const float4*)(g_cb + (size_t)bestc * DDIM))[t];
    ((float4*)(zq + (size_t)r * DDIM))[t] = cv;
    float4 st = make_float4(xv.x + (cv.x - xv.x), xv.y + (cv.y - xv.y),
                            xv.z + (cv.z - xv.z), xv.w + (cv.w - xv.w));
    ((float4*)(zqst + (size_t)r * DDIM))[t] = st;
}

__global__ void reduce_losses(float* __restrict__ scal) {
    __shared__ float scom[1024];
    __shared__ float svq[1024];
    __shared__ int   scnt[1024];
    float cm = 0.f, vq = 0.f; int cnt = 0;
    for (int r = threadIdx.x; r < NTOK; r += 1024) {
        float l = g_rowloss[r];
        cm += l;
        if (g_idx[r] >= NSEM) { vq += l; cnt++; }
    }
    scom[threadIdx.x] = cm; svq[threadIdx.x] = vq; scnt[threadIdx.x] = cnt;
    __syncthreads();
    #pragma unroll
    for (int off = 512; off; off >>= 1) {
        if (threadIdx.x < off) {
            scom[threadIdx.x] += scom[threadIdx.x + off];
            svq[threadIdx.x]  += svq[threadIdx.x + off];
            scnt[threadIdx.x] += scnt[threadIdx.x + off];
        }
        __syncthreads();
    }
    if (threadIdx.x == 0) {
        float commitment = scom[0] / (float)NTOK;
        float vql = svq[0] / ((float)scnt[0] + 1e-6f);
        scal[0] = vql;
        scal[1] = commitment;
        scal[2] = vql + 0.25f * commitment;
    }
}

// ---------------------------------------------------------------------------
extern "C" void kernel_launch(void* const* d_in, const int* in_sizes, int n_in,
                              void* d_out, int out_size) {
    const float* x   = (const float*)d_in[0];
    const float* sem = (const float*)d_in[1];
    const float* lrn = (const float*)d_in[2];
    float* out = (float*)d_out;

    float* logits = out;
    float* idxf   = out  + (size_t)NTOK * NCB;
    float* zq     = idxf + NTOK;
    float* zqst   = zq   + (size_t)NTOK * DDIM;
    float* scal   = zqst + (size_t)NTOK * DDIM;

    float *p_xn, *p_cb;
    __half *p_A, *p_B;
    cudaGetSymbolAddress((void**)&p_xn, g_xn);
    cudaGetSymbolAddress((void**)&p_cb, g_cb);
    cudaGetSymbolAddress((void**)&p_A,  g_Ah);
    cudaGetSymbolAddress((void**)&p_B,  g_Bh);

    // gemm_mma at launch index 3: ncu captures the 4th launch
    norm_cast<<<NTOK, 256>>>(x,   p_xn, p_A);                                        // 0
    norm_cast<<<NSEM, 256>>>(sem, p_cb, p_B);                                        // 1
    norm_cast<<<NLRN, 256>>>(lrn, p_cb + (size_t)NSEM * DDIM,
                             p_B + (size_t)NSEM * DDIM);                             // 2

    cudaFuncSetAttribute(gemm_mma, cudaFuncAttributeMaxDynamicSharedMemorySize, SMEM_TOTAL);
    dim3 grid(33, NTOK / TILE_M);   // 33 x 64 CTAs; bx<=31 do 2 tiles, bx=32 does 1
    gemm_mma<<<grid, 128, SMEM_TOTAL>>>(p_A, p_B, logits);                           // 3

    rescore_gather<<<NTOK, 256>>>(idxf, zq, zqst);                                   // 4
    reduce_losses<<<1, 1024>>>(scal);                                                // 5
}

// round 13
// speedup vs baseline: 1.0304x; 1.0304x over previous
#include <cuda_runtime.h>
#include <cuda_fp16.h>
#include <math.h>
#include <stdint.h>

#define NTOK 8192
#define DDIM 1024
#define NSEM 8192
#define NLRN 128
#define NCB  8320           // NSEM + NLRN = 65 * 128 exactly
#define NXT  65             // column tiles (exact, no padding)
#define NCAND (NXT * 2)     // 130 top-2-per-tile candidates per row

#define TILE_M 128
#define TILE_N 128
#define BK     64           // fp16 elems per K-chunk (128B row)
#define NKCH   (DDIM / BK)  // 16
#define STAGES 3
#define A_BYTES (TILE_M * 128)            // 16KB
#define B_BYTES (TILE_N * 128)            // 16KB
#define STAGE_BYTES (A_BYTES + B_BYTES)   // 32KB
#define RED_BYTES 4096
#define SMEM_TOTAL (STAGES * STAGE_BYTES + RED_BYTES)  // 100KB -> 2 CTAs/SM

// ---------------- scratch (__device__ globals; no allocs) -------------------
__device__ __align__(128) float  g_xn[(size_t)NTOK * DDIM];
__device__ __align__(128) float  g_cb[(size_t)NCB * DDIM];
__device__ __align__(128) __half g_Ah[(size_t)NTOK * DDIM];
__device__ __align__(128) __half g_Bh[(size_t)NCB * DDIM];
__device__ float g_p2val[(size_t)NTOK * NCAND];
__device__ int   g_p2col[(size_t)NTOK * NCAND];
__device__ float g_rowloss[NTOK];
__device__ int   g_idx[NTOK];
__device__ unsigned g_done;     // zero-initialized; reset by last block each run

// ---------------- PTX helpers ----------------------------------------------
__device__ __forceinline__ uint32_t smem_u32(const void* p) {
    uint32_t a;
    asm("{ .reg .u64 t; cvta.to.shared.u64 t, %1; cvt.u32.u64 %0, t; }" : "=r"(a) : "l"(p));
    return a;
}
__device__ __forceinline__ uint32_t sw128(uint32_t x) { return x ^ ((x >> 3) & 0x70); }

__device__ __forceinline__ void cp_async16(uint32_t dst, const void* src) {
    asm volatile("cp.async.cg.shared.global [%0], [%1], 16;" :: "r"(dst), "l"(src) : "memory");
}
#define CP_COMMIT() asm volatile("cp.async.commit_group;" ::: "memory")
#define CP_WAIT(n)  asm volatile("cp.async.wait_group %0;" :: "n"(n) : "memory")

#define LDSM_X4(r0, r1, r2, r3, a) \
    asm volatile("ldmatrix.sync.aligned.m8n8.x4.shared.b16 {%0,%1,%2,%3}, [%4];" \
                 : "=r"(r0), "=r"(r1), "=r"(r2), "=r"(r3) : "r"(a))

#define MMA16816(c, a, b0, b1) \
    asm volatile("mma.sync.aligned.m16n8k16.row.col.f32.f16.f16.f32 " \
                 "{%0,%1,%2,%3},{%4,%5,%6,%7},{%8,%9},{%0,%1,%2,%3};" \
                 : "+f"((c)[0]), "+f"((c)[1]), "+f"((c)[2]), "+f"((c)[3]) \
                 : "r"((a)[0]), "r"((a)[1]), "r"((a)[2]), "r"((a)[3]), "r"(b0), "r"(b1))

// top-2 insert keeping (value desc, col asc) order
#define TOP2_INS(v, c, v1, c1, v2, c2) do {                                  \
    float _v = (v); int _c = (c);                                            \
    if (_v > (v1) || (_v == (v1) && _c < (c1))) {                            \
        (v2) = (v1); (c2) = (c1); (v1) = _v; (c1) = _c;                      \
    } else if (_v > (v2) || (_v == (v2) && _c < (c2))) {                     \
        (v2) = _v; (c2) = _c;                                                \
    }                                                                        \
} while (0)

// ---------------------------------------------------------------------------
// merged row L2-normalize for all three tensors -> f32 copy + fp16 copy
// ---------------------------------------------------------------------------
__global__ void norm_cast_all(const float* __restrict__ x,
                              const float* __restrict__ sem,
                              const float* __restrict__ lrn) {
    int r = blockIdx.x;
    int t = threadIdx.x;
    const float* src;
    float* fdst;
    __half* hdst;
    if (r < NTOK) {
        src = x + (size_t)r * DDIM;
        fdst = g_xn + (size_t)r * DDIM;
        hdst = g_Ah + (size_t)r * DDIM;
    } else if (r < NTOK + NSEM) {
        int q = r - NTOK;
        src = sem + (size_t)q * DDIM;
        fdst = g_cb + (size_t)q * DDIM;
        hdst = g_Bh + (size_t)q * DDIM;
    } else {
        int q = r - NTOK - NSEM;
        src = lrn + (size_t)q * DDIM;
        fdst = g_cb + (size_t)(NSEM + q) * DDIM;
        hdst = g_Bh + (size_t)(NSEM + q) * DDIM;
    }
    float4 v = ((const float4*)src)[t];
    float ss = v.x * v.x + v.y * v.y + v.z * v.z + v.w * v.w;
    #pragma unroll
    for (int o = 16; o; o >>= 1) ss += __shfl_xor_sync(0xffffffffu, ss, o);
    __shared__ float red[8];
    __shared__ float inv_s;
    if ((t & 31) == 0) red[t >> 5] = ss;
    __syncthreads();
    if (t == 0) {
        float s = 0.f;
        #pragma unroll
        for (int i = 0; i < 8; i++) s += red[i];
        inv_s = 1.0f / fmaxf(sqrtf(s), 1e-8f);
    }
    __syncthreads();
    float inv = inv_s;
    float f[4] = { v.x * inv, v.y * inv, v.z * inv, v.w * inv };
    ((float4*)fdst)[t] = *(float4*)f;
    union { __half h[4]; uint2 u; } p;
    #pragma unroll
    for (int j = 0; j < 4; j++) p.h[j] = __float2half_rn(f[j]);
    *(uint2*)(hdst + 4 * t) = p.u;
}

// ---------------------------------------------------------------------------
// fp16 mma.sync GEMM (K=1024) + fused per-tile top-2 row argmax.
// CTA 128x128, 4 warps (2x2), warp tile 64x64, BK=64, 3-stage cp.async,
// 2 CTAs/SM, two column tiles per CTA in one continuous pipeline.
// (R10 configuration — best measured: GEMM ~395us, tensor 58.5%)
// ---------------------------------------------------------------------------
__device__ __forceinline__ void load_chunk(const __half* __restrict__ Ah,
                                           const __half* __restrict__ Bh,
                                           uint32_t data_base, int stage,
                                           int by, int bxe, int kc, int tid) {
    uint32_t sb = data_base + stage * STAGE_BYTES;
    const char* Ab = (const char*)Ah + (size_t)by * TILE_M * (DDIM * 2) + (size_t)kc * 128;
    const char* Bb = (const char*)Bh + (size_t)bxe * TILE_N * (DDIM * 2) + (size_t)kc * 128;
    #pragma unroll
    for (int i = 0; i < 8; i++) {
        int c = tid + i * 128;          // 0..1023
        int row = c >> 3, cg = c & 7;
        cp_async16(sb + sw128(row * 128 + cg * 16),
                   Ab + (size_t)row * (DDIM * 2) + cg * 16);
    }
    #pragma unroll
    for (int i = 0; i < 8; i++) {
        int c = tid + i * 128;
        int row = c >> 3, cg = c & 7;
        cp_async16(sb + A_BYTES + sw128(row * 128 + cg * 16),
                   Bb + (size_t)row * (DDIM * 2) + cg * 16);
    }
    CP_COMMIT();
}

__global__ void __launch_bounds__(128, 2)
gemm_mma(const __half* __restrict__ Ah, const __half* __restrict__ Bh,
         float* __restrict__ Cout) {
    extern __shared__ char smem[];
    uint32_t data_base = smem_u32(smem);
    float* bufv = (float*)(smem + STAGES * STAGE_BYTES);          // [128][2][2]
    int*   bufi = (int*)(smem + STAGES * STAGE_BYTES + 2048);     // [128][2][2]

    int tid = threadIdx.x, wid = tid >> 5, lane = tid & 31;
    int bx = blockIdx.x, by = blockIdx.y;
    int warp_m = wid & 1;       // 2 warps over M (64 rows each)
    int warp_n = wid >> 1;      // 2 warps over N (64 cols each)

    int rowA = lane & 15;
    int kselA = (lane >> 4) * 16;
    int rowB = (lane & 7) + ((lane >> 4) & 1) * 8;
    int kselB = ((lane >> 3) & 1) * 16;

    int ntiles = (bx <= 31) ? 2 : 1;       // bx in 0..32; pair (bx, bx+33)
    int NKT = ntiles * NKCH;

    float acc[4][8][4];
    #pragma unroll
    for (int i = 0; i < 4; i++)
        #pragma unroll
        for (int j = 0; j < 8; j++)
            #pragma unroll
            for (int q = 0; q < 4; q++) acc[i][j][q] = 0.f;

    load_chunk(Ah, Bh, data_base, 0, by, bx, 0, tid);
    load_chunk(Ah, Bh, data_base, 1, by, bx, 1, tid);

    for (int g = 0; g < NKT; g++) {
        if (g + 1 < NKT) CP_WAIT(1); else CP_WAIT(0);
        __syncthreads();
        if (g + 2 < NKT) {
            int gi = g + 2;
            load_chunk(Ah, Bh, data_base, gi % STAGES, by, bx + (gi >> 4) * 33,
                       gi & (NKCH - 1), tid);
        }
        uint32_t Ab = data_base + (g % STAGES) * STAGE_BYTES;
        uint32_t Bb = Ab + A_BYTES;
        #pragma unroll
        for (int ks = 0; ks < 4; ks++) {
            uint32_t afr[4][4];
            #pragma unroll
            for (int mt = 0; mt < 4; mt++) {
                uint32_t off = (uint32_t)(warp_m * 64 + mt * 16 + rowA) * 128
                             + ks * 32 + kselA;
                LDSM_X4(afr[mt][0], afr[mt][1], afr[mt][2], afr[mt][3], Ab + sw128(off));
            }
            uint32_t bfr[4][4];
            #pragma unroll
            for (int np = 0; np < 4; np++) {
                uint32_t off = (uint32_t)(warp_n * 64 + np * 16 + rowB) * 128
                             + ks * 32 + kselB;
                LDSM_X4(bfr[np][0], bfr[np][1], bfr[np][2], bfr[np][3], Bb + sw128(off));
            }
            #pragma unroll
            for (int mt = 0; mt < 4; mt++)
                #pragma unroll
                for (int nt = 0; nt < 8; nt++)
                    MMA16816(acc[mt][nt], afr[mt],
                             bfr[nt >> 1][(nt & 1) * 2], bfr[nt >> 1][(nt & 1) * 2 + 1]);
        }

        if ((g & (NKCH - 1)) == (NKCH - 1)) {
            // ============ epilogue for tile (g>>4); overlaps next tile's loads
            int bxe = bx + (g >> 4) * 33;
            int row_base = by * TILE_M + warp_m * 64;
            int col_base = bxe * TILE_N + warp_n * 64;
            #pragma unroll
            for (int mt = 0; mt < 4; mt++) {
                int r0 = row_base + mt * 16 + (lane >> 2);
                #pragma unroll
                for (int nt = 0; nt < 8; nt++) {
                    int c0 = col_base + nt * 8 + (lane & 3) * 2;
                    float2* p0 = (float2*)(Cout + (size_t)r0 * NCB + c0);
                    float2* p1 = (float2*)(Cout + (size_t)(r0 + 8) * NCB + c0);
                    *p0 = make_float2(acc[mt][nt][0], acc[mt][nt][1]);
                    *p1 = make_float2(acc[mt][nt][2], acc[mt][nt][3]);
                }
            }
            #pragma unroll
            for (int mt = 0; mt < 4; mt++) {
                #pragma unroll
                for (int h = 0; h < 2; h++) {
                    float v1 = -1e30f, v2 = -1e30f;
                    int   c1 = 0x7fffffff, c2 = 0x7fffffff;
                    #pragma unroll
                    for (int nt = 0; nt < 8; nt++) {
                        #pragma unroll
                        for (int qq = 0; qq < 2; qq++) {
                            int colg = col_base + nt * 8 + (lane & 3) * 2 + qq;
                            float v = acc[mt][nt][h * 2 + qq];
                            TOP2_INS(v, colg, v1, c1, v2, c2);
                        }
                    }
                    #pragma unroll
                    for (int off = 1; off <= 2; off <<= 1) {
                        float ov1 = __shfl_xor_sync(0xffffffffu, v1, off);
                        int   oc1 = __shfl_xor_sync(0xffffffffu, c1, off);
                        float ov2 = __shfl_xor_sync(0xffffffffu, v2, off);
                        int   oc2 = __shfl_xor_sync(0xffffffffu, c2, off);
                        TOP2_INS(ov1, oc1, v1, c1, v2, c2);
                        TOP2_INS(ov2, oc2, v1, c1, v2, c2);
                    }
                    if ((lane & 3) == 0) {
                        int rl = warp_m * 64 + mt * 16 + (lane >> 2) + h * 8;
                        bufv[(rl * 2 + warp_n) * 2 + 0] = v1;
                        bufv[(rl * 2 + warp_n) * 2 + 1] = v2;
                        bufi[(rl * 2 + warp_n) * 2 + 0] = c1;
                        bufi[(rl * 2 + warp_n) * 2 + 1] = c2;
                    }
                }
            }
            __syncthreads();
            {
                float v1 = -1e30f, v2 = -1e30f;
                int   c1 = 0x7fffffff, c2 = 0x7fffffff;
                #pragma unroll
                for (int w = 0; w < 2; w++) {
                    TOP2_INS(bufv[(tid * 2 + w) * 2 + 0], bufi[(tid * 2 + w) * 2 + 0], v1, c1, v2, c2);
                    TOP2_INS(bufv[(tid * 2 + w) * 2 + 1], bufi[(tid * 2 + w) * 2 + 1], v1, c1, v2, c2);
                }
                size_t base = ((size_t)(by * TILE_M + tid) * NXT + bxe) * 2;
                g_p2val[base + 0] = v1; g_p2val[base + 1] = v2;
                g_p2col[base + 0] = c1; g_p2col[base + 1] = c2;
            }
            __syncthreads();   // protect bufv/bufi before next tile's epilogue
            #pragma unroll
            for (int i = 0; i < 4; i++)
                #pragma unroll
                for (int j = 0; j < 8; j++)
                    #pragma unroll
                    for (int q = 0; q < 4; q++) acc[i][j][q] = 0.f;
        }
    }
}

// ---------------------------------------------------------------------------
// exact rescoring of near-max candidates (fp64 dot) + gather z_q / z_q_st,
// with the loss reduction fused via last-block-done (deterministic fixed tree).
// ---------------------------------------------------------------------------
__global__ void rescore_gather(float* __restrict__ idx_out,
                               float* __restrict__ zq,
                               float* __restrict__ zqst,
                               float* __restrict__ scal) {
    int r = blockIdx.x;
    int t = threadIdx.x;
    __shared__ float  cval[NCAND];
    __shared__ int    ccol[NCAND];
    __shared__ float  smax;
    __shared__ int    ncand;
    __shared__ int    clist[NCAND];
    __shared__ double dred[256];
    __shared__ double sbest;
    __shared__ int    sbestc;
    __shared__ int    slast;

    if (t < NCAND) {
        cval[t] = g_p2val[(size_t)r * NCAND + t];
        ccol[t] = g_p2col[(size_t)r * NCAND + t];
    }
    if (t == 0) ncand = 0;
    __syncthreads();
    if (t == 0) {
        float m = -1e30f;
        #pragma unroll
        for (int i = 0; i < NCAND; i++) m = fmaxf(m, cval[i]);
        smax = m;
    }
    __syncthreads();
    if (t < NCAND && cval[t] >= smax - 1.5e-4f && ccol[t] < NCB) {
        int s = atomicAdd(&ncand, 1);
        clist[s] = ccol[t];
    }
    __syncthreads();

    int n = ncand;
    double bestv = -1e30; int bestc = 0x7fffffff;
    const float4 xv = ((const float4*)(g_xn + (size_t)r * DDIM))[t];
    for (int i = 0; i < n; i++) {
        int c = clist[i];
        const float4 cv = ((const float4*)(g_cb + (size_t)c * DDIM))[t];
        double d = (double)xv.x * cv.x + (double)xv.y * cv.y
                 + (double)xv.z * cv.z + (double)xv.w * cv.w;
        dred[t] = d;
        __syncthreads();
        #pragma unroll
        for (int off = 128; off; off >>= 1) {
            if (t < off) dred[t] += dred[t + off];
            __syncthreads();
        }
        double tot = dred[0];
        __syncthreads();
        if (tot > bestv || (tot == bestv && c < bestc)) { bestv = tot; bestc = c; }
    }
    if (t == 0) { sbest = bestv; sbestc = bestc; }
    __syncthreads();
    bestc = sbestc; bestv = sbest;

    if (t == 0) {
        idx_out[r]   = (float)bestc;
        g_idx[r]     = bestc;
        g_rowloss[r] = 1.0f - (float)bestv;
    }
    const float4 cv = ((const float4*)(g_cb + (size_t)bestc * DDIM))[t];
    ((float4*)(zq + (size_t)r * DDIM))[t] = cv;
    float4 st = make_float4(xv.x + (cv.x - xv.x), xv.y + (cv.y - xv.y),
                            xv.z + (cv.z - xv.z), xv.w + (cv.w - xv.w));
    ((float4*)(zqst + (size_t)r * DDIM))[t] = st;

    // ---- fused loss reduction: last block to finish does it ----
    __syncthreads();
    if (t == 0) {
        __threadfence();
        unsigned prev = atomicAdd(&g_done, 1u);
        slast = (prev == NTOK - 1) ? 1 : 0;
    }
    __syncthreads();
    if (slast) {
        __shared__ float scom[256];
        __shared__ float svq[256];
        __shared__ int   scnt[256];
        float cm = 0.f, vq = 0.f; int cnt = 0;
        for (int rr = t; rr < NTOK; rr += 256) {
            float l = g_rowloss[rr];
            cm += l;
            if (g_idx[rr] >= NSEM) { vq += l; cnt++; }
        }
        scom[t] = cm; svq[t] = vq; scnt[t] = cnt;
        __syncthreads();
        #pragma unroll
        for (int off = 128; off; off >>= 1) {
            if (t < off) {
                scom[t] += scom[t + off];
                svq[t]  += svq[t + off];
                scnt[t] += scnt[t + off];
            }
            __syncthreads();
        }
        if (t == 0) {
            float commitment = scom[0] / (float)NTOK;
            float vql = svq[0] / ((float)scnt[0] + 1e-6f);
            scal[0] = vql;
            scal[1] = commitment;
            scal[2] = vql + 0.25f * commitment;
            g_done = 0;              // reset for next graph replay
        }
    }
}

// ---------------------------------------------------------------------------
extern "C" void kernel_launch(void* const* d_in, const int* in_sizes, int n_in,
                              void* d_out, int out_size) {
    const float* x   = (const float*)d_in[0];
    const float* sem = (const float*)d_in[1];
    const float* lrn = (const float*)d_in[2];
    float* out = (float*)d_out;

    float* logits = out;
    float* idxf   = out  + (size_t)NTOK * NCB;
    float* zq     = idxf + NTOK;
    float* zqst   = zq   + (size_t)NTOK * DDIM;
    float* scal   = zqst + (size_t)NTOK * DDIM;

    __half *p_A, *p_B;
    cudaGetSymbolAddress((void**)&p_A, g_Ah);
    cudaGetSymbolAddress((void**)&p_B, g_Bh);

    norm_cast_all<<<NTOK + NSEM + NLRN, 256>>>(x, sem, lrn);

    cudaFuncSetAttribute(gemm_mma, cudaFuncAttributeMaxDynamicSharedMemorySize, SMEM_TOTAL);
    dim3 grid(33, NTOK / TILE_M);   // 33 x 64 CTAs; bx<=31 do 2 tiles, bx=32 does 1
    gemm_mma<<<grid, 128, SMEM_TOTAL>>>(p_A, p_B, logits);

    rescore_gather<<<NTOK, 256>>>(idxf, zq, zqst, scal);
}

// round 14
// speedup vs baseline: 1.0993x; 1.0669x over previous
#include <cuda_runtime.h>
#include <cuda_fp16.h>
#include <math.h>
#include <stdint.h>

#define NTOK 8192
#define DDIM 1024
#define NSEM 8192
#define NLRN 128
#define NCB  8320           // NSEM + NLRN = 65 * 128 exactly
#define NXT  65             // column tiles (exact, no padding)
#define NCAND (NXT * 2)     // 130 top-2-per-tile candidates per row
#define NTILES (64 * 65)    // 4160
#define NPC   304           // persistent CTAs (2/SM x 152 SMs)

#define TILE_M 128
#define TILE_N 128
#define BK     64           // fp16 elems per K-chunk (128B row)
#define NKCH   (DDIM / BK)  // 16
#define STAGES 3
#define A_BYTES (TILE_M * 128)            // 16KB
#define B_BYTES (TILE_N * 128)            // 16KB
#define STAGE_BYTES (A_BYTES + B_BYTES)   // 32KB
#define RED_BYTES 4096
#define SMEM_TOTAL (STAGES * STAGE_BYTES + RED_BYTES)  // 100KB -> 2 CTAs/SM

// ---------------- scratch (__device__ globals; no allocs) -------------------
__device__ __align__(128) float  g_xn[(size_t)NTOK * DDIM];
__device__ __align__(128) float  g_cb[(size_t)NCB * DDIM];
__device__ __align__(128) __half g_Ah[(size_t)NTOK * DDIM];
__device__ __align__(128) __half g_Bh[(size_t)NCB * DDIM];
__device__ float g_p2val[(size_t)NTOK * NCAND];
__device__ int   g_p2col[(size_t)NTOK * NCAND];
__device__ float g_rowloss[NTOK];
__device__ int   g_idx[NTOK];
__device__ unsigned g_done;     // zero-initialized; reset by last block each run

// ---------------- PTX helpers ----------------------------------------------
__device__ __forceinline__ uint32_t smem_u32(const void* p) {
    uint32_t a;
    asm("{ .reg .u64 t; cvta.to.shared.u64 t, %1; cvt.u32.u64 %0, t; }" : "=r"(a) : "l"(p));
    return a;
}
__device__ __forceinline__ uint32_t sw128(uint32_t x) { return x ^ ((x >> 3) & 0x70); }

__device__ __forceinline__ void cp_async16(uint32_t dst, const void* src) {
    asm volatile("cp.async.cg.shared.global [%0], [%1], 16;" :: "r"(dst), "l"(src) : "memory");
}
#define CP_COMMIT() asm volatile("cp.async.commit_group;" ::: "memory")
#define CP_WAIT(n)  asm volatile("cp.async.wait_group %0;" :: "n"(n) : "memory")

#define LDSM_X4(r0, r1, r2, r3, a) \
    asm volatile("ldmatrix.sync.aligned.m8n8.x4.shared.b16 {%0,%1,%2,%3}, [%4];" \
                 : "=r"(r0), "=r"(r1), "=r"(r2), "=r"(r3) : "r"(a))

#define MMA16816(c, a, b0, b1) \
    asm volatile("mma.sync.aligned.m16n8k16.row.col.f32.f16.f16.f32 " \
                 "{%0,%1,%2,%3},{%4,%5,%6,%7},{%8,%9},{%0,%1,%2,%3};" \
                 : "+f"((c)[0]), "+f"((c)[1]), "+f"((c)[2]), "+f"((c)[3]) \
                 : "r"((a)[0]), "r"((a)[1]), "r"((a)[2]), "r"((a)[3]), "r"(b0), "r"(b1))

// top-2 insert keeping (value desc, col asc) order
#define TOP2_INS(v, c, v1, c1, v2, c2) do {                                  \
    float _v = (v); int _c = (c);                                            \
    if (_v > (v1) || (_v == (v1) && _c < (c1))) {                            \
        (v2) = (v1); (c2) = (c1); (v1) = _v; (c1) = _c;                      \
    } else if (_v > (v2) || (_v == (v2) && _c < (c2))) {                     \
        (v2) = _v; (c2) = _c;                                                \
    }                                                                        \
} while (0)

// ---------------------------------------------------------------------------
// merged row L2-normalize for all three tensors -> f32 copy + fp16 copy
// ---------------------------------------------------------------------------
__global__ void norm_cast_all(const float* __restrict__ x,
                              const float* __restrict__ sem,
                              const float* __restrict__ lrn) {
    int r = blockIdx.x;
    int t = threadIdx.x;
    const float* src;
    float* fdst;
    __half* hdst;
    if (r < NTOK) {
        src = x + (size_t)r * DDIM;
        fdst = g_xn + (size_t)r * DDIM;
        hdst = g_Ah + (size_t)r * DDIM;
    } else if (r < NTOK + NSEM) {
        int q = r - NTOK;
        src = sem + (size_t)q * DDIM;
        fdst = g_cb + (size_t)q * DDIM;
        hdst = g_Bh + (size_t)q * DDIM;
    } else {
        int q = r - NTOK - NSEM;
        src = lrn + (size_t)q * DDIM;
        fdst = g_cb + (size_t)(NSEM + q) * DDIM;
        hdst = g_Bh + (size_t)(NSEM + q) * DDIM;
    }
    float4 v = ((const float4*)src)[t];
    float ss = v.x * v.x + v.y * v.y + v.z * v.z + v.w * v.w;
    #pragma unroll
    for (int o = 16; o; o >>= 1) ss += __shfl_xor_sync(0xffffffffu, ss, o);
    __shared__ float red[8];
    __shared__ float inv_s;
    if ((t & 31) == 0) red[t >> 5] = ss;
    __syncthreads();
    if (t == 0) {
        float s = 0.f;
        #pragma unroll
        for (int i = 0; i < 8; i++) s += red[i];
        inv_s = 1.0f / fmaxf(sqrtf(s), 1e-8f);
    }
    __syncthreads();
    float inv = inv_s;
    float f[4] = { v.x * inv, v.y * inv, v.z * inv, v.w * inv };
    ((float4*)fdst)[t] = *(float4*)f;
    union { __half h[4]; uint2 u; } p;
    #pragma unroll
    for (int j = 0; j < 4; j++) p.h[j] = __float2half_rn(f[j]);
    *(uint2*)(hdst + 4 * t) = p.u;
}

__global__ void noop_k() {}

// ---------------------------------------------------------------------------
// STATIC-PERSISTENT fp16 mma.sync GEMM (K=1024) + fused top-2 row argmax.
// grid 304 (2/SM); CTA b owns tiles b, b+304, ... (13-14 tiles) in ONE
// continuous 3-stage cp.async pipeline; epilogues overlap next tile's loads.
// CTA 128x128, 4 warps (2x2), warp tile 64x64 (R10-best mainloop, unchanged).
// ---------------------------------------------------------------------------
__device__ __forceinline__ void load_chunk(const __half* __restrict__ Ah,
                                           const __half* __restrict__ Bh,
                                           uint32_t data_base, int stage,
                                           int by, int bxe, int kc, int tid) {
    uint32_t sb = data_base + stage * STAGE_BYTES;
    const char* Ab = (const char*)Ah + (size_t)by * TILE_M * (DDIM * 2) + (size_t)kc * 128;
    const char* Bb = (const char*)Bh + (size_t)bxe * TILE_N * (DDIM * 2) + (size_t)kc * 128;
    #pragma unroll
    for (int i = 0; i < 8; i++) {
        int c = tid + i * 128;          // 0..1023
        int row = c >> 3, cg = c & 7;
        cp_async16(sb + sw128(row * 128 + cg * 16),
                   Ab + (size_t)row * (DDIM * 2) + cg * 16);
    }
    #pragma unroll
    for (int i = 0; i < 8; i++) {
        int c = tid + i * 128;
        int row = c >> 3, cg = c & 7;
        cp_async16(sb + A_BYTES + sw128(row * 128 + cg * 16),
                   Bb + (size_t)row * (DDIM * 2) + cg * 16);
    }
    CP_COMMIT();
}

__global__ void __launch_bounds__(128, 2)
gemm_mma(const __half* __restrict__ Ah, const __half* __restrict__ Bh,
         float* __restrict__ Cout) {
    extern __shared__ char smem[];
    uint32_t data_base = smem_u32(smem);
    float* bufv = (float*)(smem + STAGES * STAGE_BYTES);          // [128][2][2]
    int*   bufi = (int*)(smem + STAGES * STAGE_BYTES + 2048);     // [128][2][2]

    int tid = threadIdx.x, wid = tid >> 5, lane = tid & 31;
    int bid = blockIdx.x;
    int warp_m = wid & 1;       // 2 warps over M (64 rows each)
    int warp_n = wid >> 1;      // 2 warps over N (64 cols each)

    int rowA = lane & 15;
    int kselA = (lane >> 4) * 16;
    int rowB = (lane & 7) + ((lane >> 4) & 1) * 8;
    int kselB = ((lane >> 3) & 1) * 16;

    int nt = (NTILES - bid + NPC - 1) / NPC;   // 13 or 14 tiles
    int NKT = nt * NKCH;

    float acc[4][8][4];
    #pragma unroll
    for (int i = 0; i < 4; i++)
        #pragma unroll
        for (int j = 0; j < 8; j++)
            #pragma unroll
            for (int q = 0; q < 4; q++) acc[i][j][q] = 0.f;

    {
        int t0 = bid;
        load_chunk(Ah, Bh, data_base, 0, t0 / NXT, t0 % NXT, 0, tid);
        load_chunk(Ah, Bh, data_base, 1, t0 / NXT, t0 % NXT, 1, tid);
    }

    for (int g = 0; g < NKT; g++) {
        if (g + 1 < NKT) CP_WAIT(1); else CP_WAIT(0);
        __syncthreads();
        if (g + 2 < NKT) {
            int gi = g + 2;
            int tp = bid + (gi >> 4) * NPC;
            load_chunk(Ah, Bh, data_base, gi % STAGES, tp / NXT, tp % NXT,
                       gi & (NKCH - 1), tid);
        }
        uint32_t Ab = data_base + (g % STAGES) * STAGE_BYTES;
        uint32_t Bb = Ab + A_BYTES;
        #pragma unroll
        for (int ks = 0; ks < 4; ks++) {
            uint32_t afr[4][4];
            #pragma unroll
            for (int mt = 0; mt < 4; mt++) {
                uint32_t off = (uint32_t)(warp_m * 64 + mt * 16 + rowA) * 128
                             + ks * 32 + kselA;
                LDSM_X4(afr[mt][0], afr[mt][1], afr[mt][2], afr[mt][3], Ab + sw128(off));
            }
            uint32_t bfr[4][4];
            #pragma unroll
            for (int np = 0; np < 4; np++) {
                uint32_t off = (uint32_t)(warp_n * 64 + np * 16 + rowB) * 128
                             + ks * 32 + kselB;
                LDSM_X4(bfr[np][0], bfr[np][1], bfr[np][2], bfr[np][3], Bb + sw128(off));
            }
            #pragma unroll
            for (int mt = 0; mt < 4; mt++)
                #pragma unroll
                for (int nt2 = 0; nt2 < 8; nt2++)
                    MMA16816(acc[mt][nt2], afr[mt],
                             bfr[nt2 >> 1][(nt2 & 1) * 2], bfr[nt2 >> 1][(nt2 & 1) * 2 + 1]);
        }

        if ((g & (NKCH - 1)) == (NKCH - 1)) {
            // ============ epilogue for tile bid + (g>>4)*NPC; overlaps next loads
            int tcur = bid + (g >> 4) * NPC;
            int by = tcur / NXT, bxe = tcur % NXT;
            int row_base = by * TILE_M + warp_m * 64;
            int col_base = bxe * TILE_N + warp_n * 64;
            #pragma unroll
            for (int mt = 0; mt < 4; mt++) {
                int r0 = row_base + mt * 16 + (lane >> 2);
                #pragma unroll
                for (int nt2 = 0; nt2 < 8; nt2++) {
                    int c0 = col_base + nt2 * 8 + (lane & 3) * 2;
                    float2* p0 = (float2*)(Cout + (size_t)r0 * NCB + c0);
                    float2* p1 = (float2*)(Cout + (size_t)(r0 + 8) * NCB + c0);
                    *p0 = make_float2(acc[mt][nt2][0], acc[mt][nt2][1]);
                    *p1 = make_float2(acc[mt][nt2][2], acc[mt][nt2][3]);
                }
            }
            #pragma unroll
            for (int mt = 0; mt < 4; mt++) {
                #pragma unroll
                for (int h = 0; h < 2; h++) {
                    float v1 = -1e30f, v2 = -1e30f;
                    int   c1 = 0x7fffffff, c2 = 0x7fffffff;
                    #pragma unroll
                    for (int nt2 = 0; nt2 < 8; nt2++) {
                        #pragma unroll
                        for (int qq = 0; qq < 2; qq++) {
                            int colg = col_base + nt2 * 8 + (lane & 3) * 2 + qq;
                            float v = acc[mt][nt2][h * 2 + qq];
                            TOP2_INS(v, colg, v1, c1, v2, c2);
                        }
                    }
                    #pragma unroll
                    for (int off = 1; off <= 2; off <<= 1) {
                        float ov1 = __shfl_xor_sync(0xffffffffu, v1, off);
                        int   oc1 = __shfl_xor_sync(0xffffffffu, c1, off);
                        float ov2 = __shfl_xor_sync(0xffffffffu, v2, off);
                        int   oc2 = __shfl_xor_sync(0xffffffffu, c2, off);
                        TOP2_INS(ov1, oc1, v1, c1, v2, c2);
                        TOP2_INS(ov2, oc2, v1, c1, v2, c2);
                    }
                    if ((lane & 3) == 0) {
                        int rl = warp_m * 64 + mt * 16 + (lane >> 2) + h * 8;
                        bufv[(rl * 2 + warp_n) * 2 + 0] = v1;
                        bufv[(rl * 2 + warp_n) * 2 + 1] = v2;
                        bufi[(rl * 2 + warp_n) * 2 + 0] = c1;
                        bufi[(rl * 2 + warp_n) * 2 + 1] = c2;
                    }
                }
            }
            __syncthreads();
            {
                float v1 = -1e30f, v2 = -1e30f;
                int   c1 = 0x7fffffff, c2 = 0x7fffffff;
                #pragma unroll
                for (int w = 0; w < 2; w++) {
                    TOP2_INS(bufv[(tid * 2 + w) * 2 + 0], bufi[(tid * 2 + w) * 2 + 0], v1, c1, v2, c2);
                    TOP2_INS(bufv[(tid * 2 + w) * 2 + 1], bufi[(tid * 2 + w) * 2 + 1], v1, c1, v2, c2);
                }
                size_t base = ((size_t)(by * TILE_M + tid) * NXT + bxe) * 2;
                g_p2val[base + 0] = v1; g_p2val[base + 1] = v2;
                g_p2col[base + 0] = c1; g_p2col[base + 1] = c2;
            }
            __syncthreads();   // protect bufv/bufi before next tile's epilogue
            #pragma unroll
            for (int i = 0; i < 4; i++)
                #pragma unroll
                for (int j = 0; j < 8; j++)
                    #pragma unroll
                    for (int q = 0; q < 4; q++) acc[i][j][q] = 0.f;
        }
    }
}

// ---------------------------------------------------------------------------
// exact rescoring of near-max candidates + gather z_q / z_q_st + fused losses.
// FAST PATH: if only one candidate is within the margin, it IS the exact
// argmax (margin 1.5e-4 >> 2x fp16-GEMM logit error) — skip the fp64 pass.
// ---------------------------------------------------------------------------
__global__ void rescore_gather(float* __restrict__ idx_out,
                               float* __restrict__ zq,
                               float* __restrict__ zqst,
                               float* __restrict__ scal) {
    int r = blockIdx.x;
    int t = threadIdx.x;
    __shared__ float  cval[NCAND];
    __shared__ int    ccol[NCAND];
    __shared__ float  smax;
    __shared__ int    ncand;
    __shared__ int    clist[NCAND];
    __shared__ double dred[256];
    __shared__ double sbest;
    __shared__ int    sbestc;
    __shared__ int    slast;

    if (t < NCAND) {
        cval[t] = g_p2val[(size_t)r * NCAND + t];
        ccol[t] = g_p2col[(size_t)r * NCAND + t];
    }
    if (t == 0) ncand = 0;
    __syncthreads();
    if (t == 0) {
        float m = -1e30f;
        #pragma unroll
        for (int i = 0; i < NCAND; i++) m = fmaxf(m, cval[i]);
        smax = m;
    }
    __syncthreads();
    if (t < NCAND && cval[t] >= smax - 1.5e-4f && ccol[t] < NCB) {
        int s = atomicAdd(&ncand, 1);
        clist[s] = ccol[t];
    }
    __syncthreads();

    int n = ncand;
    double bestv; int bestc;
    const float4 xv = ((const float4*)(g_xn + (size_t)r * DDIM))[t];
    if (n == 1) {
        bestc = clist[0];
        bestv = (double)smax;
    } else {
        bestv = -1e30; bestc = 0x7fffffff;
        for (int i = 0; i < n; i++) {
            int c = clist[i];
            const float4 cv = ((const float4*)(g_cb + (size_t)c * DDIM))[t];
            double d = (double)xv.x * cv.x + (double)xv.y * cv.y
                     + (double)xv.z * cv.z + (double)xv.w * cv.w;
            dred[t] = d;
            __syncthreads();
            #pragma unroll
            for (int off = 128; off; off >>= 1) {
                if (t < off) dred[t] += dred[t + off];
                __syncthreads();
            }
            double tot = dred[0];
            __syncthreads();
            if (tot > bestv || (tot == bestv && c < bestc)) { bestv = tot; bestc = c; }
        }
        if (t == 0) { sbest = bestv; sbestc = bestc; }
        __syncthreads();
        bestc = sbestc; bestv = sbest;
    }

    if (t == 0) {
        idx_out[r]   = (float)bestc;
        g_idx[r]     = bestc;
        g_rowloss[r] = 1.0f - (float)bestv;
    }
    const float4 cv = ((const float4*)(g_cb + (size_t)bestc * DDIM))[t];
    ((float4*)(zq + (size_t)r * DDIM))[t] = cv;
    float4 st = make_float4(xv.x + (cv.x - xv.x), xv.y + (cv.y - xv.y),
                            xv.z + (cv.z - xv.z), xv.w + (cv.w - xv.w));
    ((float4*)(zqst + (size_t)r * DDIM))[t] = st;

    // ---- fused loss reduction: last block to finish does it ----
    __syncthreads();
    if (t == 0) {
        __threadfence();
        unsigned prev = atomicAdd(&g_done, 1u);
        slast = (prev == NTOK - 1) ? 1 : 0;
    }
    __syncthreads();
    if (slast) {
        __shared__ float scom[256];
        __shared__ float svq[256];
        __shared__ int   scnt[256];
        float cm = 0.f, vq = 0.f; int cnt = 0;
        for (int rr = t; rr < NTOK; rr += 256) {
            float l = g_rowloss[rr];
            cm += l;
            if (g_idx[rr] >= NSEM) { vq += l; cnt++; }
        }
        scom[t] = cm; svq[t] = vq; scnt[t] = cnt;
        __syncthreads();
        #pragma unroll
        for (int off = 128; off; off >>= 1) {
            if (t < off) {
                scom[t] += scom[t + off];
                svq[t]  += svq[t + off];
                scnt[t] += scnt[t + off];
            }
            __syncthreads();
        }
        if (t == 0) {
            float commitment = scom[0] / (float)NTOK;
            float vql = svq[0] / ((float)scnt[0] + 1e-6f);
            scal[0] = vql;
            scal[1] = commitment;
            scal[2] = vql + 0.25f * commitment;
            g_done = 0;              // reset for next graph replay
        }
    }
}

// ---------------------------------------------------------------------------
extern "C" void kernel_launch(void* const* d_in, const int* in_sizes, int n_in,
                              void* d_out, int out_size) {
    const float* x   = (const float*)d_in[0];
    const float* sem = (const float*)d_in[1];
    const float* lrn = (const float*)d_in[2];
    float* out = (float*)d_out;

    float* logits = out;
    float* idxf   = out  + (size_t)NTOK * NCB;
    float* zq     = idxf + NTOK;
    float* zqst   = zq   + (size_t)NTOK * DDIM;
    float* scal   = zqst + (size_t)NTOK * DDIM;

    __half *p_A, *p_B;
    cudaGetSymbolAddress((void**)&p_A, g_Ah);
    cudaGetSymbolAddress((void**)&p_B, g_Bh);

    // gemm at user-launch index 3 (ncu captures index 3)
    norm_cast_all<<<NTOK + NSEM + NLRN, 256>>>(x, sem, lrn);     // 0
    noop_k<<<1, 32>>>();                                         // 1
    noop_k<<<1, 32>>>();                                         // 2

    cudaFuncSetAttribute(gemm_mma, cudaFuncAttributeMaxDynamicSharedMemorySize, SMEM_TOTAL);
    gemm_mma<<<NPC, 128, SMEM_TOTAL>>>(p_A, p_B, logits);        // 3

    rescore_gather<<<NTOK, 256>>>(idxf, zq, zqst, scal);         // 4
}